// round 9
// baseline (speedup 1.0000x reference)
#include <cuda_runtime.h>
#include <math.h>

#define BATCH 2048
#define XF    1024
#define XF4   (XF / 4)
#define G     16

#define NBLK  512
#define CH    64                // row chunks
#define RPCH  (BATCH / CH)      // 32 rows per chunk
#define RPT   4                 // rows per thread (8 subgroups x 4)

// Scratch (allocation-free: __device__ globals)
__device__ float g_p0[CH * XF];
__device__ float g_p1[CH * XF];
__device__ float g_p2[CH * XF];
__device__ float g_mean[XF];

__device__ unsigned g_count = 0;
__device__ unsigned g_gen   = 0;   // monotone generation (replay-safe)

__device__ __forceinline__ void grid_barrier() {
    __syncthreads();
    if (threadIdx.x == 0) {
        volatile unsigned* genp = (volatile unsigned*)&g_gen;
        unsigned gen = *genp;
        __threadfence();
        if (atomicAdd(&g_count, 1u) == NBLK - 1u) {
            g_count = 0;                 // safe: nobody re-arrives until gen bumps
            __threadfence();
            *genp = gen + 1u;            // release
        } else {
            while (*genp == gen) { }
        }
        __threadfence();
    }
    __syncthreads();
}

// ---------------------------------------------------------------------------
// Kernel A: sum partials -> barrier -> mean fold + stats partials.
// grid = 512: b = col-group (8 x 32 float4) * chunk (64 x 32 rows).
__global__ __launch_bounds__(256, 4)
void kA_stats(const float* __restrict__ xf) {
    __shared__ float4 sh[8][32];
    __shared__ float4 shm[32];

    const int tid = threadIdx.x;
    const int c4 = tid & 31, rg = tid >> 5;
    const int cg = blockIdx.x & 7, chunk = blockIdx.x >> 3;
    const int col4 = cg * 32 + c4;
    const int row0 = chunk * RPCH + rg * RPT;

    // ---- Phase 1: column sums over this chunk's 32 rows ----
    {
        const float4* p = (const float4*)xf + (size_t)row0 * XF4 + col4;
        float4 s = make_float4(0.f, 0.f, 0.f, 0.f);
#pragma unroll
        for (int r = 0; r < RPT; r++) {
            float4 x = p[(size_t)r * XF4];
            s.x += x.x; s.y += x.y; s.z += x.z; s.w += x.w;
        }
        sh[rg][c4] = s;
        __syncthreads();
        if (rg == 0) {
            float4 t = sh[0][c4];
#pragma unroll
            for (int i = 1; i < 8; i++) {
                float4 u = sh[i][c4];
                t.x += u.x; t.y += u.y; t.z += u.z; t.w += u.w;
            }
            ((float4*)(g_p0 + chunk * XF))[col4] = t;
        }
    }
    grid_barrier();

    // ---- Phase 2: fold 64 mean-partials in-block, then stats ----
    {
        float4 s = make_float4(0.f, 0.f, 0.f, 0.f);
#pragma unroll
        for (int i = 0; i < 8; i++) {        // rg folds chunks rg*8..rg*8+7
            float4 u = ((const float4*)(g_p0 + (rg * 8 + i) * XF))[col4];
            s.x += u.x; s.y += u.y; s.z += u.z; s.w += u.w;
        }
        sh[rg][c4] = s;
        __syncthreads();
        if (rg == 0) {
            float4 t = sh[0][c4];
#pragma unroll
            for (int i = 1; i < 8; i++) {
                float4 u = sh[i][c4];
                t.x += u.x; t.y += u.y; t.z += u.z; t.w += u.w;
            }
            const float inv = 1.0f / BATCH;
            t.x *= inv; t.y *= inv; t.z *= inv; t.w *= inv;
            shm[c4] = t;
            if (chunk == 0) ((float4*)g_mean)[col4] = t;
        }
        __syncthreads();
        float4 m = shm[c4];

        const float4* p = (const float4*)xf + (size_t)row0 * XF4 + col4;
        float4 s1 = make_float4(0.f, 0.f, 0.f, 0.f);
        float4 s2 = make_float4(0.f, 0.f, 0.f, 0.f);
#pragma unroll
        for (int r = 0; r < RPT; r++) {
            float4 x = p[(size_t)r * XF4];
            float vx = fmaxf(x.x - m.x, 0.f);
            float vy = fmaxf(x.y - m.y, 0.f);
            float vz = fmaxf(x.z - m.z, 0.f);
            float vw = fmaxf(x.w - m.w, 0.f);
            s1.x += vx; s1.y += vy; s1.z += vz; s1.w += vw;
            s2.x += vx * vx; s2.y += vy * vy; s2.z += vz * vz; s2.w += vw * vw;
        }
        __syncthreads();
        sh[rg][c4] = s1;
        __syncthreads();
        if (rg == 0) {
            float4 t = sh[0][c4];
#pragma unroll
            for (int i = 1; i < 8; i++) {
                float4 u = sh[i][c4];
                t.x += u.x; t.y += u.y; t.z += u.z; t.w += u.w;
            }
            ((float4*)(g_p1 + chunk * XF))[col4] = t;
        }
        __syncthreads();
        sh[rg][c4] = s2;
        __syncthreads();
        if (rg == 0) {
            float4 t = sh[0][c4];
#pragma unroll
            for (int i = 1; i < 8; i++) {
                float4 u = sh[i][c4];
                t.x += u.x; t.y += u.y; t.z += u.z; t.w += u.w;
            }
            ((float4*)(g_p2 + chunk * XF))[col4] = t;
        }
    }
}

// ---------------------------------------------------------------------------
// Kernel B: fold stats partials for its 64 columns -> (a,b); write 16-way
// tiled output with streaming stores. grid=(16,16), block=256. (R7 shape.)
#define COLS_B 64
#define ROWS_B 128
__global__ __launch_bounds__(256) void kB_out(const float* __restrict__ xf,
                                              const float* __restrict__ wp,
                                              float* __restrict__ out) {
    __shared__ float sh1[4][COLS_B], sh2[4][COLS_B];
    __shared__ float s_m[COLS_B], s_a[COLS_B], s_b[COLS_B];
    int tid = threadIdx.x;
    int col0 = blockIdx.x * COLS_B;

    {   // fold: cc = col, gg folds 16 chunks each
        int cc = tid & 63, gg = tid >> 6;
        int col = col0 + cc;
        float s1 = 0.f, s2 = 0.f;
#pragma unroll
        for (int i = 0; i < 16; i++) {
            int idx = (gg * 16 + i) * XF + col;
            s1 += g_p1[idx];
            s2 += g_p2[idx];
        }
        sh1[gg][cc] = s1;
        sh2[gg][cc] = s2;
    }
    __syncthreads();
    if (tid < COLS_B) {
        float s1 = sh1[0][tid] + sh1[1][tid] + sh1[2][tid] + sh1[3][tid];
        float s2 = sh2[0][tid] + sh2[1][tid] + sh2[2][tid] + sh2[3][tid];
        float mu  = s1 * (1.0f / BATCH);
        float var = (s2 - (float)BATCH * mu * mu) * (1.0f / (BATCH - 1));
        float a   = wp[0] * rsqrtf(var);
        s_m[tid] = g_mean[col0 + tid];
        s_a[tid] = a;
        s_b[tid] = -a * mu;
    }
    __syncthreads();

    int cidx = tid & 15;
    int ridx = tid >> 4;
    int col  = col0 + cidx * 4;

    float4 m = *(const float4*)(s_m + cidx * 4);
    float4 a = *(const float4*)(s_a + cidx * 4);
    float4 b = *(const float4*)(s_b + cidx * 4);

#pragma unroll
    for (int j = 0; j < ROWS_B / 16; j++) {     // 8 rows per thread
        int row = blockIdx.y * ROWS_B + ridx + j * 16;
        float4 x = *(const float4*)(xf + (size_t)row * XF + col);
        float4 v;
        v.x = fmaxf(x.x - m.x, 0.f) * a.x + b.x;
        v.y = fmaxf(x.y - m.y, 0.f) * a.y + b.y;
        v.z = fmaxf(x.z - m.z, 0.f) * a.z + b.z;
        v.w = fmaxf(x.w - m.w, 0.f) * a.w + b.w;

        float* orow = out + (size_t)row * (G * XF) + col;
#pragma unroll
        for (int k = 0; k < G; k++)
            __stcs((float4*)(orow + (size_t)k * XF), v);
    }
}

extern "C" void kernel_launch(void* const* d_in, const int* in_sizes, int n_in,
                              void* d_out, int out_size) {
    const float* xf = (const float*)d_in[0];
    const float* wp = (const float*)d_in[1];
    float* out = (float*)d_out;

    kA_stats<<<NBLK, 256>>>(xf);
    kB_out<<<dim3(XF / COLS_B, BATCH / ROWS_B), 256>>>(xf, wp, out);
}